// round 9
// baseline (speedup 1.0000x reference)
#include <cuda_runtime.h>
#include <cuda_fp16.h>
#include <cstdint>

#define BN_EPS 1e-5f

// ======================= device scratch (no allocs allowed) =================
static __device__ __half g_xh[1024 * 256];                // x hi, K padded to 256
static __device__ __half g_xl[1024 * 256];                // x lo
static __device__ __half g_w0th[2048 * 256];              // W0^T hi [2048][256]
static __device__ __half g_w0tl[2048 * 256];              // W0^T lo
static __device__ __half g_hh[1024 * 2048];               // trunk hidden hi
static __device__ __half g_hl[1024 * 2048];               // trunk hidden lo
static __device__ __half g_w1th[1024 * 2048];             // W1^T hi [1024][2048]
static __device__ __half g_w1tl[1024 * 2048];             // W1^T lo
static __device__ __half g_fh[1024 * 1024];               // feats fp16
static __device__ __half g_hw1t[128u * 512u * 1024u];     // HW1^T [n][512][1024]
static __device__ __half g_hw2t[128u * 256u * 512u];      // HW2^T [n][256][512]
static __device__ __half g_zh[128u * 1024u * 512u];       // z fp16 [n][1024][512]
static __device__ float g_a0[2048], g_bb0[2048];
static __device__ float g_a1[1024], g_bb1[1024];

// ======================= small helpers ======================================
__device__ __forceinline__ uint32_t smem_to_u32(const void* p) {
    uint32_t a;
    asm("{ .reg .u64 t; cvta.to.shared.u64 t, %1; cvt.u32.u64 %0, t; }" : "=r"(a) : "l"(p));
    return a;
}
__device__ __forceinline__ uint32_t swz128(uint32_t off) {
    return off ^ ((off >> 3) & 0x70);
}
__device__ __forceinline__ void cp_async16(uint32_t dst, const void* src) {
    asm volatile("cp.async.cg.shared.global [%0], [%1], 16;" :: "r"(dst), "l"(src));
}
#define CP_COMMIT() asm volatile("cp.async.commit_group;" ::: "memory")
#define CP_WAIT(n)  asm volatile("cp.async.wait_group %0;" :: "n"(n) : "memory")

#define LDMX4(r, addr) \
    asm volatile("ldmatrix.sync.aligned.m8n8.x4.shared.b16 {%0,%1,%2,%3}, [%4];" \
        : "=r"((r)[0]), "=r"((r)[1]), "=r"((r)[2]), "=r"((r)[3]) : "r"(addr))

#define MMA_F16(d, a, b0_, b1_) \
    asm volatile("mma.sync.aligned.m16n8k16.row.col.f32.f16.f16.f32 " \
        "{%0,%1,%2,%3}, {%4,%5,%6,%7}, {%8,%9}, {%0,%1,%2,%3};" \
        : "+f"((d)[0]), "+f"((d)[1]), "+f"((d)[2]), "+f"((d)[3]) \
        : "r"((a)[0]), "r"((a)[1]), "r"((a)[2]), "r"((a)[3]), "r"(b0_), "r"(b1_))

__device__ __forceinline__ uint32_t pack_h2(__half lo16, __half hi16) {
    return ((uint32_t)__half_as_ushort(hi16) << 16) | __half_as_ushort(lo16);
}

// ================= fused prep: BN fold + converts + transposes ==============
__device__ __forceinline__ void tp64(const float* __restrict__ in,
                                     __half* __restrict__ oh, __half* __restrict__ ol,
                                     int R, int C, int Rpad, int r0, int c0,
                                     float* t, int tid) {
#pragma unroll
    for (int k = 0; k < 4; k++) {
        const int u = tid + k * 256;
        const int r = u >> 4;
        const int cq = (u & 15) * 4;
        const int gr = r0 + r;
        float4 v = make_float4(0.f, 0.f, 0.f, 0.f);
        if (gr < R) v = *(const float4*)(in + (long long)gr * C + c0 + cq);
        t[r * 65 + cq]     = v.x;
        t[r * 65 + cq + 1] = v.y;
        t[r * 65 + cq + 2] = v.z;
        t[r * 65 + cq + 3] = v.w;
    }
    __syncthreads();
#pragma unroll
    for (int k = 0; k < 8; k++) {
        const int u = tid + k * 256;
        const int cc = u >> 5;
        const int rq = (u & 31) * 2;
        const float v0 = t[rq * 65 + cc];
        const float v1 = t[(rq + 1) * 65 + cc];
        const __half h0 = __float2half(v0), h1 = __float2half(v1);
        const long long o = (long long)(c0 + cc) * Rpad + r0 + rq;
        *(uint32_t*)(oh + o) = pack_h2(h0, h1);
        if (ol)
            *(uint32_t*)(ol + o) = pack_h2(__float2half(v0 - __half2float(h0)),
                                           __float2half(v1 - __half2float(h1)));
    }
}

// segments: bnfold 8 | xconv 512 | W0T 128 | W1T 512 | HW1T 16384 | HW2T 4096
__global__ __launch_bounds__(256)
void prep_all_kernel(const float* __restrict__ x,
                     const float* __restrict__ W0, const float* __restrict__ W1,
                     const float* __restrict__ HW1, const float* __restrict__ HW2,
                     const float* __restrict__ b0, const float* __restrict__ g0,
                     const float* __restrict__ be0, const float* __restrict__ m0,
                     const float* __restrict__ v0,
                     const float* __restrict__ b1, const float* __restrict__ g1,
                     const float* __restrict__ be1, const float* __restrict__ m1,
                     const float* __restrict__ v1) {
    __shared__ float t[64 * 65];
    const int tid = threadIdx.x;
    const int b = blockIdx.x;

    if (b < 8) {
        const int i = b * 256 + tid;
        if (i < 2048) {
            float a = g0[i] / sqrtf(v0[i] + BN_EPS);
            g_a0[i]  = a;
            g_bb0[i] = be0[i] + (b0[i] - m0[i]) * a;
        }
        if (i < 1024) {
            float a = g1[i] / sqrtf(v1[i] + BN_EPS);
            g_a1[i]  = a;
            g_bb1[i] = be1[i] + (b1[i] - m1[i]) * a;
        }
    } else if (b < 520) {
        const int u = (b - 8) * 256 + tid;
        const int row = u >> 7;
        const int c2 = (u & 127) * 2;
        float v0 = (c2     < 200) ? x[row * 200 + c2]     : 0.f;
        float v1 = (c2 + 1 < 200) ? x[row * 200 + c2 + 1] : 0.f;
        __half h0 = __float2half(v0), h1 = __float2half(v1);
        *(uint32_t*)(g_xh + row * 256 + c2) = pack_h2(h0, h1);
        *(uint32_t*)(g_xl + row * 256 + c2) =
            pack_h2(__float2half(v0 - __half2float(h0)),
                    __float2half(v1 - __half2float(h1)));
    } else if (b < 648) {
        const int i = b - 520;
        const int by = i >> 5, bx = i & 31;
        tp64(W0, g_w0th, g_w0tl, 200, 2048, 256, by * 64, bx * 64, t, tid);
    } else if (b < 1160) {
        const int i = b - 648;
        const int by = i >> 4, bx = i & 15;
        tp64(W1, g_w1th, g_w1tl, 2048, 1024, 2048, by * 64, bx * 64, t, tid);
    } else if (b < 17544) {
        const int i = b - 1160;
        const int head = i >> 7;
        const int rem = i & 127;
        const int by = rem >> 3, bx = rem & 7;
        tp64(HW1 + (long long)head * 1024 * 512,
             g_hw1t + (long long)head * 512 * 1024, nullptr,
             1024, 512, 1024, by * 64, bx * 64, t, tid);
    } else {
        const int i = b - 17544;
        const int head = i >> 5;
        const int rem = i & 31;
        const int by = rem >> 2, bx = rem & 3;
        tp64(HW2 + (long long)head * 512 * 256,
             g_hw2t + (long long)head * 256 * 512, nullptr,
             512, 256, 512, by * 64, bx * 64, t, tid);
    }
}

// ============ unified mma.sync GEMM, templated BM x BN ======================
// C = act( (A[+Al]) @ (B[+Bl])^T * [alpha] + beta ) ; passes AhBh(+AhBl)(+AlBh)
// 8 warps/CTA. Warp tile (BM/4) x (BN/2). K-chunk 64, double-buffered smem.
// OUTMODE: 0 = fp32, 1 = fp16 hi, 2 = fp16 hi+lo split.
template <int BM, int BN, bool SA, bool SB, bool HASALPHA, bool RELU, int OUTMODE>
__global__ __launch_bounds__(256, BM == 128 ? 2 : 1)
void hmma_gemm_kernel(const __half* __restrict__ Ah, const __half* __restrict__ Al,
                      long long sA, int lda,
                      const __half* __restrict__ Bh, const __half* __restrict__ Bl,
                      long long sB,
                      const float* __restrict__ alpha,
                      const float* __restrict__ bias, int sBias,
                      float* __restrict__ Cf, __half* __restrict__ Ch,
                      __half* __restrict__ Cl,
                      long long sC, int ldc, int K) {
    constexpr int TA = BM * 128;              // A tile bytes (BM rows x 128 B)
    constexpr int TB = BN * 128;
    constexpr int OFF_AL = TA;                // iff SA
    constexpr int OFF_B  = (SA ? 2 : 1) * TA;
    constexpr int OFF_BL = OFF_B + TB;        // iff SB
    constexpr int BUF = OFF_B + (SB ? 2 : 1) * TB;
    constexpr int RW = BM / 4;                // warp rows (32 or 64)
    constexpr int MI = RW / 16;               // m-frags (2 or 4)
    constexpr int NF = BN / 16;               // n8-frags per warp (BN/2 / 8)
    constexpr int NG = BN / 32;               // B ldmatrix groups per warp

    extern __shared__ char smem[];
    const uint32_t sb = smem_to_u32(smem);
    const int tid = threadIdx.x;
    const int lane = tid & 31;
    const int w = tid >> 5;
    const int wm = (w >> 1) * RW;
    const int wn = (w & 1) * (BN / 2);
    const int head = blockIdx.z;
    const int mBase = blockIdx.y * BM;
    const int nBase = blockIdx.x * BN;

    const __half* pA  = Ah + (long long)head * sA + (long long)mBase * lda;
    const __half* pAl = SA ? Al + (long long)head * sA + (long long)mBase * lda : nullptr;
    const __half* pB  = Bh + (long long)head * sB + (long long)nBase * K;
    const __half* pBl = SB ? Bl + (long long)head * sB + (long long)nBase * K : nullptr;

    float acc[MI][NF][4];
#pragma unroll
    for (int mi = 0; mi < MI; mi++)
#pragma unroll
        for (int n = 0; n < NF; n++)
#pragma unroll
            for (int q = 0; q < 4; q++) acc[mi][n][q] = 0.0f;

    const int nCh = K >> 6;

    auto load_chunk = [&](uint32_t buf, int kB) {
#pragma unroll
        for (int u = tid; u < BM * 8; u += 256) {
            const int r = u >> 3, c = u & 7;
            const uint32_t sw = swz128((uint32_t)(r * 128 + c * 16));
            cp_async16(buf + sw, pA + (long long)r * lda + kB + c * 8);
            if (SA) cp_async16(buf + OFF_AL + sw, pAl + (long long)r * lda + kB + c * 8);
        }
#pragma unroll
        for (int u = tid; u < BN * 8; u += 256) {
            const int r = u >> 3, c = u & 7;
            const uint32_t sw = swz128((uint32_t)(r * 128 + c * 16));
            cp_async16(buf + OFF_B + sw, pB + (long long)r * K + kB + c * 8);
            if (SB) cp_async16(buf + OFF_BL + sw, pBl + (long long)r * K + kB + c * 8);
        }
    };

    load_chunk(sb, 0);
    CP_COMMIT();

    const int aRowA = wm + (lane & 15);
    const int aRowB = wn + (lane & 15);
    const int cSel  = (lane >> 4);

    for (int c = 0; c < nCh; ++c) {
        if (c + 1 < nCh) {
            load_chunk(sb + ((c + 1) & 1) * BUF, (c + 1) * 64);
            CP_COMMIT();
            CP_WAIT(1);
        } else {
            CP_WAIT(0);
        }
        __syncthreads();

        const uint32_t bA = sb + (c & 1) * BUF;

#pragma unroll
        for (int ks = 0; ks < 4; ks++) {
            const int kc = ks * 2 + cSel;
            uint32_t ah[MI][4], al[MI][4];
#pragma unroll
            for (int mi = 0; mi < MI; mi++) {
                uint32_t ad = swz128((uint32_t)((aRowA + mi * 16) * 128 + kc * 16));
                LDMX4(ah[mi], bA + ad);
                if (SA) LDMX4(al[mi], bA + OFF_AL + ad);
            }
#pragma unroll
            for (int g = 0; g < NG; g++) {
                uint32_t bh[4], bl[4];
                uint32_t bd = swz128((uint32_t)((aRowB + g * 16) * 128 + kc * 16));
                LDMX4(bh, bA + OFF_B + bd);
                if (SB) LDMX4(bl, bA + OFF_BL + bd);
#pragma unroll
                for (int mi = 0; mi < MI; mi++) {
#pragma unroll
                    for (int s = 0; s < 2; s++) {
                        const int n = g * 2 + s;
                        MMA_F16(acc[mi][n], ah[mi], bh[s], bh[s + 2]);
                        if (SB) MMA_F16(acc[mi][n], ah[mi], bl[s], bl[s + 2]);
                        if (SA) MMA_F16(acc[mi][n], al[mi], bh[s], bh[s + 2]);
                    }
                }
            }
        }
        __syncthreads();
    }

    // -------------------------------- epilogue ------------------------------
    const float* bp = bias + (long long)head * sBias + nBase;
    const float* ap = HASALPHA ? alpha + nBase : nullptr;
#pragma unroll
    for (int mi = 0; mi < MI; mi++) {
        const int r0 = mBase + wm + mi * 16 + (lane >> 2);
#pragma unroll
        for (int n = 0; n < NF; n++) {
            const int colL = wn + n * 8 + (lane & 3) * 2;
            const float b0 = __ldg(bp + colL);
            const float b1 = __ldg(bp + colL + 1);
            float a0c = 1.0f, a1c = 1.0f;
            if (HASALPHA) { a0c = __ldg(ap + colL); a1c = __ldg(ap + colL + 1); }
#pragma unroll
            for (int rr = 0; rr < 2; rr++) {
                float v0 = HASALPHA ? fmaf(acc[mi][n][rr * 2 + 0], a0c, b0)
                                    : acc[mi][n][rr * 2 + 0] + b0;
                float v1 = HASALPHA ? fmaf(acc[mi][n][rr * 2 + 1], a1c, b1)
                                    : acc[mi][n][rr * 2 + 1] + b1;
                if (RELU) { v0 = fmaxf(v0, 0.0f); v1 = fmaxf(v1, 0.0f); }
                const long long o = (long long)head * sC +
                                    (long long)(r0 + rr * 8) * ldc + nBase + colL;
                if (OUTMODE == 0) {
                    *(float2*)(Cf + o) = make_float2(v0, v1);
                } else if (OUTMODE == 1) {
                    *(uint32_t*)(Ch + o) = pack_h2(__float2half(v0), __float2half(v1));
                } else {
                    __half h0 = __float2half(v0), h1 = __float2half(v1);
                    *(uint32_t*)(Ch + o) = pack_h2(h0, h1);
                    *(uint32_t*)(Cl + o) =
                        pack_h2(__float2half(v0 - __half2float(h0)),
                                __float2half(v1 - __half2float(h1)));
                }
            }
        }
    }
}

// ================================ launcher ==================================
extern "C" void kernel_launch(void* const* d_in, const int* in_sizes, int n_in,
                              void* d_out, int out_size) {
    const float* x   = (const float*)d_in[0];
    const float* W0  = (const float*)d_in[1];
    const float* b0  = (const float*)d_in[2];
    const float* g0  = (const float*)d_in[3];
    const float* be0 = (const float*)d_in[4];
    const float* m0  = (const float*)d_in[5];
    const float* v0  = (const float*)d_in[6];
    const float* W1  = (const float*)d_in[7];
    const float* b1  = (const float*)d_in[8];
    const float* g1  = (const float*)d_in[9];
    const float* be1 = (const float*)d_in[10];
    const float* m1  = (const float*)d_in[11];
    const float* v1  = (const float*)d_in[12];
    const float* HW1 = (const float*)d_in[13];
    const float* Hb1 = (const float*)d_in[14];
    const float* HW2 = (const float*)d_in[15];
    const float* Hb2 = (const float*)d_in[16];
    float* out = (float*)d_out;

    float *a0, *bb0, *a1, *bb1;
    __half *xh, *xl, *w0th, *w0tl, *hh, *hl, *w1th, *w1tl, *fh, *hw1t, *hw2t, *zh;
    cudaGetSymbolAddress((void**)&xh,   g_xh);
    cudaGetSymbolAddress((void**)&xl,   g_xl);
    cudaGetSymbolAddress((void**)&w0th, g_w0th);
    cudaGetSymbolAddress((void**)&w0tl, g_w0tl);
    cudaGetSymbolAddress((void**)&hh,   g_hh);
    cudaGetSymbolAddress((void**)&hl,   g_hl);
    cudaGetSymbolAddress((void**)&w1th, g_w1th);
    cudaGetSymbolAddress((void**)&w1tl, g_w1tl);
    cudaGetSymbolAddress((void**)&fh,   g_fh);
    cudaGetSymbolAddress((void**)&hw1t, g_hw1t);
    cudaGetSymbolAddress((void**)&hw2t, g_hw2t);
    cudaGetSymbolAddress((void**)&zh,   g_zh);
    cudaGetSymbolAddress((void**)&a0,   g_a0);
    cudaGetSymbolAddress((void**)&bb0,  g_bb0);
    cudaGetSymbolAddress((void**)&a1,   g_a1);
    cudaGetSymbolAddress((void**)&bb1,  g_bb1);

    cudaFuncSetAttribute(hmma_gemm_kernel<128, 64, true, true, true, true, 2>,
                         cudaFuncAttributeMaxDynamicSharedMemorySize, 98304);
    cudaFuncSetAttribute(hmma_gemm_kernel<128, 64, true, true, true, true, 1>,
                         cudaFuncAttributeMaxDynamicSharedMemorySize, 98304);
    cudaFuncSetAttribute(hmma_gemm_kernel<256, 128, false, false, false, true, 1>,
                         cudaFuncAttributeMaxDynamicSharedMemorySize, 98304);
    cudaFuncSetAttribute(hmma_gemm_kernel<256, 128, false, false, false, false, 0>,
                         cudaFuncAttributeMaxDynamicSharedMemorySize, 98304);

    // 0) single fused prep launch
    prep_all_kernel<<<21640, 256>>>(x, W0, W1, HW1, HW2,
                                    b0, g0, be0, m0, v0, b1, g1, be1, m1, v1);

    // 1) h = relu(BN(x @ W0 + b0))   3-pass split HMMA -> fp16 hi/lo
    hmma_gemm_kernel<128, 64, true, true, true, true, 2><<<dim3(32, 8, 1), 256, 98304>>>(
        xh, xl, 0LL, 256,
        w0th, w0tl, 0LL,
        a0, bb0, 0,
        nullptr, hh, hl, 0LL, 2048, 256);

    // 2) feats = relu(BN(h @ W1 + b1))  3-pass split HMMA -> fp16
    hmma_gemm_kernel<128, 64, true, true, true, true, 1><<<dim3(16, 8, 1), 256, 98304>>>(
        hh, hl, 0LL, 2048,
        w1th, w1tl, 0LL,
        a1, bb1, 0,
        nullptr, fh, nullptr, 0LL, 1024, 2048);

    // 3) z[n] = relu(feats @ HW1[n] + Hb1[n])  1-pass fp16, 256x128 tile
    hmma_gemm_kernel<256, 128, false, false, false, true, 1><<<dim3(4, 4, 128), 256, 98304>>>(
        fh, nullptr, 0LL, 1024,
        hw1t, nullptr, 512LL * 1024,
        nullptr, Hb1, 512,
        nullptr, zh, nullptr, 1024LL * 512, 512, 1024);

    // 4) out[:,n,:] = z[n] @ HW2[n] + Hb2[n]  1-pass fp16 -> fp32, 256x128 tile
    hmma_gemm_kernel<256, 128, false, false, false, false, 0><<<dim3(2, 4, 128), 256, 98304>>>(
        zh, nullptr, 1024LL * 512, 512,
        hw2t, nullptr, 256LL * 512,
        nullptr, Hb2, 256,
        out, nullptr, nullptr, 256LL, 128 * 256, 512);
}

// round 10
// speedup vs baseline: 1.1003x; 1.1003x over previous
#include <cuda_runtime.h>
#include <cuda_fp16.h>
#include <cstdint>

#define BN_EPS 1e-5f

// ======================= device scratch (no allocs allowed) =================
static __device__ __half g_xh[1024 * 256];                // x hi, K padded to 256
static __device__ __half g_xl[1024 * 256];                // x lo
static __device__ __half g_w0th[2048 * 256];              // W0^T hi [2048][256]
static __device__ __half g_w0tl[2048 * 256];              // W0^T lo
static __device__ __half g_hh[1024 * 2048];               // trunk hidden hi
static __device__ __half g_hl[1024 * 2048];               // trunk hidden lo
static __device__ __half g_w1th[1024 * 2048];             // W1^T hi [1024][2048]
static __device__ __half g_w1tl[1024 * 2048];             // W1^T lo
static __device__ __half g_fh[1024 * 1024];               // feats fp16
static __device__ __half g_hw1t[128u * 512u * 1024u];     // HW1^T [n][512][1024]
static __device__ __half g_hw2t[128u * 256u * 512u];      // HW2^T [n][256][512]
static __device__ __half g_zh[128u * 1024u * 512u];       // z fp16 [n][1024][512]
static __device__ float g_a0[2048], g_bb0[2048];
static __device__ float g_a1[1024], g_bb1[1024];

// ======================= small helpers ======================================
__device__ __forceinline__ uint32_t smem_to_u32(const void* p) {
    uint32_t a;
    asm("{ .reg .u64 t; cvta.to.shared.u64 t, %1; cvt.u32.u64 %0, t; }" : "=r"(a) : "l"(p));
    return a;
}
__device__ __forceinline__ uint32_t swz128(uint32_t off) {
    return off ^ ((off >> 3) & 0x70);
}
__device__ __forceinline__ void cp_async16(uint32_t dst, const void* src) {
    asm volatile("cp.async.cg.shared.global [%0], [%1], 16;" :: "r"(dst), "l"(src));
}
#define CP_COMMIT() asm volatile("cp.async.commit_group;" ::: "memory")
#define CP_WAIT(n)  asm volatile("cp.async.wait_group %0;" :: "n"(n) : "memory")

#define LDMX4(r, addr) \
    asm volatile("ldmatrix.sync.aligned.m8n8.x4.shared.b16 {%0,%1,%2,%3}, [%4];" \
        : "=r"((r)[0]), "=r"((r)[1]), "=r"((r)[2]), "=r"((r)[3]) : "r"(addr))

#define MMA_F16(d, a, b0_, b1_) \
    asm volatile("mma.sync.aligned.m16n8k16.row.col.f32.f16.f16.f32 " \
        "{%0,%1,%2,%3}, {%4,%5,%6,%7}, {%8,%9}, {%0,%1,%2,%3};" \
        : "+f"((d)[0]), "+f"((d)[1]), "+f"((d)[2]), "+f"((d)[3]) \
        : "r"((a)[0]), "r"((a)[1]), "r"((a)[2]), "r"((a)[3]), "r"(b0_), "r"(b1_))

__device__ __forceinline__ uint32_t pack_h2(__half lo16, __half hi16) {
    return ((uint32_t)__half_as_ushort(hi16) << 16) | __half_as_ushort(lo16);
}

// ================= fused prep: BN fold + converts + transposes ==============
__device__ __forceinline__ void tp64(const float* __restrict__ in,
                                     __half* __restrict__ oh, __half* __restrict__ ol,
                                     int R, int C, int Rpad, int r0, int c0,
                                     float* t, int tid) {
#pragma unroll
    for (int k = 0; k < 4; k++) {
        const int u = tid + k * 256;
        const int r = u >> 4;
        const int cq = (u & 15) * 4;
        const int gr = r0 + r;
        float4 v = make_float4(0.f, 0.f, 0.f, 0.f);
        if (gr < R) v = *(const float4*)(in + (long long)gr * C + c0 + cq);
        t[r * 65 + cq]     = v.x;
        t[r * 65 + cq + 1] = v.y;
        t[r * 65 + cq + 2] = v.z;
        t[r * 65 + cq + 3] = v.w;
    }
    __syncthreads();
#pragma unroll
    for (int k = 0; k < 8; k++) {
        const int u = tid + k * 256;
        const int cc = u >> 5;
        const int rq = (u & 31) * 2;
        const float v0 = t[rq * 65 + cc];
        const float v1 = t[(rq + 1) * 65 + cc];
        const __half h0 = __float2half(v0), h1 = __float2half(v1);
        const long long o = (long long)(c0 + cc) * Rpad + r0 + rq;
        *(uint32_t*)(oh + o) = pack_h2(h0, h1);
        if (ol)
            *(uint32_t*)(ol + o) = pack_h2(__float2half(v0 - __half2float(h0)),
                                           __float2half(v1 - __half2float(h1)));
    }
}

// segments: bnfold 8 | xconv 512 | W0T 128 | W1T 512 | HW1T 16384 | HW2T 4096
__global__ __launch_bounds__(256)
void prep_all_kernel(const float* __restrict__ x,
                     const float* __restrict__ W0, const float* __restrict__ W1,
                     const float* __restrict__ HW1, const float* __restrict__ HW2,
                     const float* __restrict__ b0, const float* __restrict__ g0,
                     const float* __restrict__ be0, const float* __restrict__ m0,
                     const float* __restrict__ v0,
                     const float* __restrict__ b1, const float* __restrict__ g1,
                     const float* __restrict__ be1, const float* __restrict__ m1,
                     const float* __restrict__ v1) {
    __shared__ float t[64 * 65];
    const int tid = threadIdx.x;
    const int b = blockIdx.x;

    if (b < 8) {
        const int i = b * 256 + tid;
        if (i < 2048) {
            float a = g0[i] / sqrtf(v0[i] + BN_EPS);
            g_a0[i]  = a;
            g_bb0[i] = be0[i] + (b0[i] - m0[i]) * a;
        }
        if (i < 1024) {
            float a = g1[i] / sqrtf(v1[i] + BN_EPS);
            g_a1[i]  = a;
            g_bb1[i] = be1[i] + (b1[i] - m1[i]) * a;
        }
    } else if (b < 520) {
        const int u = (b - 8) * 256 + tid;
        const int row = u >> 7;
        const int c2 = (u & 127) * 2;
        float v0 = (c2     < 200) ? x[row * 200 + c2]     : 0.f;
        float v1 = (c2 + 1 < 200) ? x[row * 200 + c2 + 1] : 0.f;
        __half h0 = __float2half(v0), h1 = __float2half(v1);
        *(uint32_t*)(g_xh + row * 256 + c2) = pack_h2(h0, h1);
        *(uint32_t*)(g_xl + row * 256 + c2) =
            pack_h2(__float2half(v0 - __half2float(h0)),
                    __float2half(v1 - __half2float(h1)));
    } else if (b < 648) {
        const int i = b - 520;
        const int by = i >> 5, bx = i & 31;
        tp64(W0, g_w0th, g_w0tl, 200, 2048, 256, by * 64, bx * 64, t, tid);
    } else if (b < 1160) {
        const int i = b - 648;
        const int by = i >> 4, bx = i & 15;
        tp64(W1, g_w1th, g_w1tl, 2048, 1024, 2048, by * 64, bx * 64, t, tid);
    } else if (b < 17544) {
        const int i = b - 1160;
        const int head = i >> 7;
        const int rem = i & 127;
        const int by = rem >> 3, bx = rem & 7;
        tp64(HW1 + (long long)head * 1024 * 512,
             g_hw1t + (long long)head * 512 * 1024, nullptr,
             1024, 512, 1024, by * 64, bx * 64, t, tid);
    } else {
        const int i = b - 17544;
        const int head = i >> 5;
        const int rem = i & 31;
        const int by = rem >> 2, bx = rem & 3;
        tp64(HW2 + (long long)head * 512 * 256,
             g_hw2t + (long long)head * 256 * 512, nullptr,
             512, 256, 512, by * 64, bx * 64, t, tid);
    }
}

// ============ unified mma.sync GEMM, BM=128, templated BN ===================
// C = act( (A[+Al]) @ (B[+Bl])^T * [alpha] + beta ) ; passes AhBh(+AhBl)(+AlBh)
// 8 warps/CTA, warp tile 32 x (BN/2). K-chunk 64, double-buffered smem,
// register-level pipelining of ldmatrix (prefetch next B group / next-ks A).
// OUTMODE: 0 = fp32, 1 = fp16 hi, 2 = fp16 hi+lo split.
template <int BN, bool SA, bool SB, bool HASALPHA, bool RELU, int OUTMODE>
__global__ __launch_bounds__(256, 2)
void hmma_gemm_kernel(const __half* __restrict__ Ah, const __half* __restrict__ Al,
                      long long sA, int lda,
                      const __half* __restrict__ Bh, const __half* __restrict__ Bl,
                      long long sB,
                      const float* __restrict__ alpha,
                      const float* __restrict__ bias, int sBias,
                      float* __restrict__ Cf, __half* __restrict__ Ch,
                      __half* __restrict__ Cl,
                      long long sC, int ldc, int K) {
    constexpr int TA = 16384;                 // 128 rows x 128 B
    constexpr int TB = BN * 128;
    constexpr int OFF_AL = TA;                // iff SA
    constexpr int OFF_B  = (SA ? 2 : 1) * TA;
    constexpr int OFF_BL = OFF_B + TB;        // iff SB
    constexpr int BUF = OFF_B + (SB ? 2 : 1) * TB;
    constexpr int NF = BN / 16;               // n8-frags per warp
    constexpr int NG = BN / 32;               // B ldmatrix groups per warp

    extern __shared__ char smem[];
    const uint32_t sb = smem_to_u32(smem);
    const int tid = threadIdx.x;
    const int lane = tid & 31;
    const int w = tid >> 5;
    const int wm = (w >> 1) * 32;
    const int wn = (w & 1) * (BN / 2);
    const int head = blockIdx.z;
    const int mBase = blockIdx.y * 128;
    const int nBase = blockIdx.x * BN;

    const __half* pA  = Ah + (long long)head * sA + (long long)mBase * lda;
    const __half* pAl = SA ? Al + (long long)head * sA + (long long)mBase * lda : nullptr;
    const __half* pB  = Bh + (long long)head * sB + (long long)nBase * K;
    const __half* pBl = SB ? Bl + (long long)head * sB + (long long)nBase * K : nullptr;

    float acc[2][NF][4];
#pragma unroll
    for (int mi = 0; mi < 2; mi++)
#pragma unroll
        for (int n = 0; n < NF; n++)
#pragma unroll
            for (int q = 0; q < 4; q++) acc[mi][n][q] = 0.0f;

    const int nCh = K >> 6;

    auto load_chunk = [&](uint32_t buf, int kB) {
#pragma unroll
        for (int u = tid; u < 1024; u += 256) {       // A rows: 128
            const int r = u >> 3, c = u & 7;
            const uint32_t sw = swz128((uint32_t)(r * 128 + c * 16));
            cp_async16(buf + sw, pA + (long long)r * lda + kB + c * 8);
            if (SA) cp_async16(buf + OFF_AL + sw, pAl + (long long)r * lda + kB + c * 8);
        }
#pragma unroll
        for (int u = tid; u < BN * 8; u += 256) {     // B rows: BN
            const int r = u >> 3, c = u & 7;
            const uint32_t sw = swz128((uint32_t)(r * 128 + c * 16));
            cp_async16(buf + OFF_B + sw, pB + (long long)r * K + kB + c * 8);
            if (SB) cp_async16(buf + OFF_BL + sw, pBl + (long long)r * K + kB + c * 8);
        }
    };

    load_chunk(sb, 0);
    CP_COMMIT();

    const int aRowA = wm + (lane & 15);
    const int aRowB = wn + (lane & 15);
    const int cSel  = (lane >> 4);

    for (int c = 0; c < nCh; ++c) {
        if (c + 1 < nCh) {
            load_chunk(sb + ((c + 1) & 1) * BUF, (c + 1) * 64);
            CP_COMMIT();
            CP_WAIT(1);
        } else {
            CP_WAIT(0);
        }
        __syncthreads();

        const uint32_t bA = sb + (c & 1) * BUF;

        // register double-buffered frags
        uint32_t ah[2][2][4], al[2][2][4];
        uint32_t bh[2][4], bl[2][4];

        auto ldA = [&](int pb, int ks) {
            const int kc = ks * 2 + cSel;
#pragma unroll
            for (int mi = 0; mi < 2; mi++) {
                const uint32_t ad = swz128((uint32_t)((aRowA + mi * 16) * 128 + kc * 16));
                LDMX4(ah[pb][mi], bA + ad);
                if (SA) LDMX4(al[pb][mi], bA + OFF_AL + ad);
            }
        };
        auto ldB = [&](int pb, int ks, int g) {
            const int kc = ks * 2 + cSel;
            const uint32_t bd = swz128((uint32_t)((aRowB + g * 16) * 128 + kc * 16));
            LDMX4(bh[pb], bA + OFF_B + bd);
            if (SB) LDMX4(bl[pb], bA + OFF_BL + bd);
        };

        ldA(0, 0);
        ldB(0, 0, 0);
#pragma unroll
        for (int step = 0; step < 4 * NG; step++) {
            const int ks = step / NG, g = step % NG;
            const int nstep = step + 1;
            if (nstep < 4 * NG) {
                const int nks = nstep / NG, ng2 = nstep % NG;
                if (ng2 == 0) ldA(nks & 1, nks);
                ldB(nstep & 1, nks, ng2);
            }
            const int ab = ks & 1, bb = step & 1;
#pragma unroll
            for (int mi = 0; mi < 2; mi++)
#pragma unroll
                for (int s = 0; s < 2; s++) {
                    const int n = g * 2 + s;
                    MMA_F16(acc[mi][n], ah[ab][mi], bh[bb][s], bh[bb][s + 2]);
                    if (SB) MMA_F16(acc[mi][n], ah[ab][mi], bl[bb][s], bl[bb][s + 2]);
                    if (SA) MMA_F16(acc[mi][n], al[ab][mi], bh[bb][s], bh[bb][s + 2]);
                }
        }
        __syncthreads();
    }

    // -------------------------------- epilogue ------------------------------
    const float* bp = bias + (long long)head * sBias + nBase;
    const float* ap = HASALPHA ? alpha + nBase : nullptr;
#pragma unroll
    for (int mi = 0; mi < 2; mi++) {
        const int r0 = mBase + wm + mi * 16 + (lane >> 2);
#pragma unroll
        for (int n = 0; n < NF; n++) {
            const int colL = wn + n * 8 + (lane & 3) * 2;
            const float b0 = __ldg(bp + colL);
            const float b1 = __ldg(bp + colL + 1);
            float a0c = 1.0f, a1c = 1.0f;
            if (HASALPHA) { a0c = __ldg(ap + colL); a1c = __ldg(ap + colL + 1); }
#pragma unroll
            for (int rr = 0; rr < 2; rr++) {
                float v0 = HASALPHA ? fmaf(acc[mi][n][rr * 2 + 0], a0c, b0)
                                    : acc[mi][n][rr * 2 + 0] + b0;
                float v1 = HASALPHA ? fmaf(acc[mi][n][rr * 2 + 1], a1c, b1)
                                    : acc[mi][n][rr * 2 + 1] + b1;
                if (RELU) { v0 = fmaxf(v0, 0.0f); v1 = fmaxf(v1, 0.0f); }
                const long long o = (long long)head * sC +
                                    (long long)(r0 + rr * 8) * ldc + nBase + colL;
                if (OUTMODE == 0) {
                    *(float2*)(Cf + o) = make_float2(v0, v1);
                } else if (OUTMODE == 1) {
                    *(uint32_t*)(Ch + o) = pack_h2(__float2half(v0), __float2half(v1));
                } else {
                    __half h0 = __float2half(v0), h1 = __float2half(v1);
                    *(uint32_t*)(Ch + o) = pack_h2(h0, h1);
                    *(uint32_t*)(Cl + o) =
                        pack_h2(__float2half(v0 - __half2float(h0)),
                                __float2half(v1 - __half2float(h1)));
                }
            }
        }
    }
}

// ================================ launcher ==================================
extern "C" void kernel_launch(void* const* d_in, const int* in_sizes, int n_in,
                              void* d_out, int out_size) {
    const float* x   = (const float*)d_in[0];
    const float* W0  = (const float*)d_in[1];
    const float* b0  = (const float*)d_in[2];
    const float* g0  = (const float*)d_in[3];
    const float* be0 = (const float*)d_in[4];
    const float* m0  = (const float*)d_in[5];
    const float* v0  = (const float*)d_in[6];
    const float* W1  = (const float*)d_in[7];
    const float* b1  = (const float*)d_in[8];
    const float* g1  = (const float*)d_in[9];
    const float* be1 = (const float*)d_in[10];
    const float* m1  = (const float*)d_in[11];
    const float* v1  = (const float*)d_in[12];
    const float* HW1 = (const float*)d_in[13];
    const float* Hb1 = (const float*)d_in[14];
    const float* HW2 = (const float*)d_in[15];
    const float* Hb2 = (const float*)d_in[16];
    float* out = (float*)d_out;

    float *a0, *bb0, *a1, *bb1;
    __half *xh, *xl, *w0th, *w0tl, *hh, *hl, *w1th, *w1tl, *fh, *hw1t, *hw2t, *zh;
    cudaGetSymbolAddress((void**)&xh,   g_xh);
    cudaGetSymbolAddress((void**)&xl,   g_xl);
    cudaGetSymbolAddress((void**)&w0th, g_w0th);
    cudaGetSymbolAddress((void**)&w0tl, g_w0tl);
    cudaGetSymbolAddress((void**)&hh,   g_hh);
    cudaGetSymbolAddress((void**)&hl,   g_hl);
    cudaGetSymbolAddress((void**)&w1th, g_w1th);
    cudaGetSymbolAddress((void**)&w1tl, g_w1tl);
    cudaGetSymbolAddress((void**)&fh,   g_fh);
    cudaGetSymbolAddress((void**)&hw1t, g_hw1t);
    cudaGetSymbolAddress((void**)&hw2t, g_hw2t);
    cudaGetSymbolAddress((void**)&zh,   g_zh);
    cudaGetSymbolAddress((void**)&a0,   g_a0);
    cudaGetSymbolAddress((void**)&bb0,  g_bb0);
    cudaGetSymbolAddress((void**)&a1,   g_a1);
    cudaGetSymbolAddress((void**)&bb1,  g_bb1);

    cudaFuncSetAttribute(hmma_gemm_kernel<64, true, true, true, true, 2>,
                         cudaFuncAttributeMaxDynamicSharedMemorySize, 98304);
    cudaFuncSetAttribute(hmma_gemm_kernel<64, true, true, true, true, 1>,
                         cudaFuncAttributeMaxDynamicSharedMemorySize, 98304);
    cudaFuncSetAttribute(hmma_gemm_kernel<128, false, false, false, true, 1>,
                         cudaFuncAttributeMaxDynamicSharedMemorySize, 65536);
    cudaFuncSetAttribute(hmma_gemm_kernel<128, false, false, false, false, 0>,
                         cudaFuncAttributeMaxDynamicSharedMemorySize, 65536);

    // 0) single fused prep launch
    prep_all_kernel<<<21640, 256>>>(x, W0, W1, HW1, HW2,
                                    b0, g0, be0, m0, v0, b1, g1, be1, m1, v1);

    // 1) h = relu(BN(x @ W0 + b0))   3-pass split HMMA -> fp16 hi/lo
    hmma_gemm_kernel<64, true, true, true, true, 2><<<dim3(32, 8, 1), 256, 98304>>>(
        xh, xl, 0LL, 256,
        w0th, w0tl, 0LL,
        a0, bb0, 0,
        nullptr, hh, hl, 0LL, 2048, 256);

    // 2) feats = relu(BN(h @ W1 + b1))  3-pass split HMMA -> fp16
    hmma_gemm_kernel<64, true, true, true, true, 1><<<dim3(16, 8, 1), 256, 98304>>>(
        hh, hl, 0LL, 2048,
        w1th, w1tl, 0LL,
        a1, bb1, 0,
        nullptr, fh, nullptr, 0LL, 1024, 2048);

    // 3) z[n] = relu(feats @ HW1[n] + Hb1[n])  1-pass fp16 -> fp16
    hmma_gemm_kernel<128, false, false, false, true, 1><<<dim3(4, 8, 128), 256, 65536>>>(
        fh, nullptr, 0LL, 1024,
        hw1t, nullptr, 512LL * 1024,
        nullptr, Hb1, 512,
        nullptr, zh, nullptr, 1024LL * 512, 512, 1024);

    // 4) out[:,n,:] = z[n] @ HW2[n] + Hb2[n]  1-pass fp16 -> fp32
    hmma_gemm_kernel<128, false, false, false, false, 0><<<dim3(2, 8, 128), 256, 65536>>>(
        zh, nullptr, 1024LL * 512, 512,
        hw2t, nullptr, 256LL * 512,
        nullptr, Hb2, 256,
        out, nullptr, nullptr, 256LL, 128 * 256, 512);
}

// round 11
// speedup vs baseline: 1.1100x; 1.0088x over previous
#include <cuda_runtime.h>
#include <cuda_fp16.h>
#include <cstdint>

#define BN_EPS 1e-5f

// ======================= device scratch (no allocs allowed) =================
static __device__ __half g_xh[1024 * 256];                // x hi, K padded to 256
static __device__ __half g_xl[1024 * 256];                // x lo
static __device__ __half g_w0th[2048 * 256];              // W0^T hi [2048][256]
static __device__ __half g_w0tl[2048 * 256];              // W0^T lo
static __device__ __half g_hh[1024 * 2048];               // trunk hidden hi
static __device__ __half g_hl[1024 * 2048];               // trunk hidden lo
static __device__ __half g_w1th[1024 * 2048];             // W1^T hi [1024][2048]
static __device__ __half g_w1tl[1024 * 2048];             // W1^T lo
static __device__ __half g_fh[1024 * 1024];               // feats fp16
static __device__ __half g_hw1t[128u * 512u * 1024u];     // HW1^T [n][512][1024]
static __device__ __half g_hw2t[128u * 256u * 512u];      // HW2^T [n][256][512]
static __device__ __half g_zh[128u * 1024u * 512u];       // z fp16 [n][1024][512]
static __device__ float g_a0[2048], g_bb0[2048];
static __device__ float g_a1[1024], g_bb1[1024];

// ======================= small helpers ======================================
__device__ __forceinline__ uint32_t smem_to_u32(const void* p) {
    uint32_t a;
    asm("{ .reg .u64 t; cvta.to.shared.u64 t, %1; cvt.u32.u64 %0, t; }" : "=r"(a) : "l"(p));
    return a;
}
__device__ __forceinline__ uint32_t swz128(uint32_t off) {
    return off ^ ((off >> 3) & 0x70);
}
__device__ __forceinline__ void cp_async16(uint32_t dst, const void* src) {
    asm volatile("cp.async.cg.shared.global [%0], [%1], 16;" :: "r"(dst), "l"(src));
}
#define CP_COMMIT() asm volatile("cp.async.commit_group;" ::: "memory")
#define CP_WAIT(n)  asm volatile("cp.async.wait_group %0;" :: "n"(n) : "memory")

#define LDMX4(r, addr) \
    asm volatile("ldmatrix.sync.aligned.m8n8.x4.shared.b16 {%0,%1,%2,%3}, [%4];" \
        : "=r"((r)[0]), "=r"((r)[1]), "=r"((r)[2]), "=r"((r)[3]) : "r"(addr))

#define MMA_F16(d, a, b0_, b1_) \
    asm volatile("mma.sync.aligned.m16n8k16.row.col.f32.f16.f16.f32 " \
        "{%0,%1,%2,%3}, {%4,%5,%6,%7}, {%8,%9}, {%0,%1,%2,%3};" \
        : "+f"((d)[0]), "+f"((d)[1]), "+f"((d)[2]), "+f"((d)[3]) \
        : "r"((a)[0]), "r"((a)[1]), "r"((a)[2]), "r"((a)[3]), "r"(b0_), "r"(b1_))

__device__ __forceinline__ uint32_t pack_h2(__half lo16, __half hi16) {
    return ((uint32_t)__half_as_ushort(hi16) << 16) | __half_as_ushort(lo16);
}

// ================= fused prep: BN fold + converts + transposes ==============
// 64x64-tile transpose-split, uint4 (16 B) stores on the write side.
__device__ __forceinline__ void tp64(const float* __restrict__ in,
                                     __half* __restrict__ oh, __half* __restrict__ ol,
                                     int R, int C, int Rpad, int r0, int c0,
                                     float* t, int tid) {
#pragma unroll
    for (int k = 0; k < 4; k++) {
        const int u = tid + k * 256;
        const int r = u >> 4;
        const int cq = (u & 15) * 4;
        const int gr = r0 + r;
        float4 v = make_float4(0.f, 0.f, 0.f, 0.f);
        if (gr < R) v = *(const float4*)(in + (long long)gr * C + c0 + cq);
        t[r * 65 + cq]     = v.x;
        t[r * 65 + cq + 1] = v.y;
        t[r * 65 + cq + 2] = v.z;
        t[r * 65 + cq + 3] = v.w;
    }
    __syncthreads();
#pragma unroll
    for (int k = 0; k < 2; k++) {
        const int u = tid + k * 256;
        const int cc = u >> 3;            // output row (source column) 0..63
        const int r8 = (u & 7) * 8;       // 8 consecutive output cols
        uint32_t hp[4], lp[4];
#pragma unroll
        for (int j = 0; j < 4; j++) {
            const float v0 = t[(r8 + 2 * j) * 65 + cc];
            const float v1 = t[(r8 + 2 * j + 1) * 65 + cc];
            const __half h0 = __float2half(v0), h1 = __float2half(v1);
            hp[j] = pack_h2(h0, h1);
            if (ol) lp[j] = pack_h2(__float2half(v0 - __half2float(h0)),
                                    __float2half(v1 - __half2float(h1)));
        }
        const long long o = (long long)(c0 + cc) * Rpad + r0 + r8;
        *(uint4*)(oh + o) = make_uint4(hp[0], hp[1], hp[2], hp[3]);
        if (ol) *(uint4*)(ol + o) = make_uint4(lp[0], lp[1], lp[2], lp[3]);
    }
}

// segments: bnfold 8 | xconv 512 | W0T 128 | W1T 512 | HW1T 16384 | HW2T 4096
__global__ __launch_bounds__(256)
void prep_all_kernel(const float* __restrict__ x,
                     const float* __restrict__ W0, const float* __restrict__ W1,
                     const float* __restrict__ HW1, const float* __restrict__ HW2,
                     const float* __restrict__ b0, const float* __restrict__ g0,
                     const float* __restrict__ be0, const float* __restrict__ m0,
                     const float* __restrict__ v0,
                     const float* __restrict__ b1, const float* __restrict__ g1,
                     const float* __restrict__ be1, const float* __restrict__ m1,
                     const float* __restrict__ v1) {
    __shared__ float t[64 * 65];
    const int tid = threadIdx.x;
    const int b = blockIdx.x;

    if (b < 8) {
        const int i = b * 256 + tid;
        if (i < 2048) {
            float a = g0[i] / sqrtf(v0[i] + BN_EPS);
            g_a0[i]  = a;
            g_bb0[i] = be0[i] + (b0[i] - m0[i]) * a;
        }
        if (i < 1024) {
            float a = g1[i] / sqrtf(v1[i] + BN_EPS);
            g_a1[i]  = a;
            g_bb1[i] = be1[i] + (b1[i] - m1[i]) * a;
        }
    } else if (b < 520) {
        const int u = (b - 8) * 256 + tid;
        const int row = u >> 7;
        const int c2 = (u & 127) * 2;
        float v0 = (c2     < 200) ? x[row * 200 + c2]     : 0.f;
        float v1 = (c2 + 1 < 200) ? x[row * 200 + c2 + 1] : 0.f;
        __half h0 = __float2half(v0), h1 = __float2half(v1);
        *(uint32_t*)(g_xh + row * 256 + c2) = pack_h2(h0, h1);
        *(uint32_t*)(g_xl + row * 256 + c2) =
            pack_h2(__float2half(v0 - __half2float(h0)),
                    __float2half(v1 - __half2float(h1)));
    } else if (b < 648) {
        const int i = b - 520;
        const int by = i >> 5, bx = i & 31;
        tp64(W0, g_w0th, g_w0tl, 200, 2048, 256, by * 64, bx * 64, t, tid);
    } else if (b < 1160) {
        const int i = b - 648;
        const int by = i >> 4, bx = i & 15;
        tp64(W1, g_w1th, g_w1tl, 2048, 1024, 2048, by * 64, bx * 64, t, tid);
    } else if (b < 17544) {
        const int i = b - 1160;
        const int head = i >> 7;
        const int rem = i & 127;
        const int by = rem >> 3, bx = rem & 7;
        tp64(HW1 + (long long)head * 1024 * 512,
             g_hw1t + (long long)head * 512 * 1024, nullptr,
             1024, 512, 1024, by * 64, bx * 64, t, tid);
    } else {
        const int i = b - 17544;
        const int head = i >> 5;
        const int rem = i & 31;
        const int by = rem >> 2, bx = rem & 3;
        tp64(HW2 + (long long)head * 512 * 256,
             g_hw2t + (long long)head * 256 * 512, nullptr,
             512, 256, 512, by * 64, bx * 64, t, tid);
    }
}

// ============ unified mma.sync GEMM, BM=128, templated BN / stages ==========
// C = act( (A[+Al]) @ (B[+Bl])^T * [alpha] + beta ) ; passes AhBh(+AhBl)(+AlBh)
// 8 warps/CTA, warp tile 32 x (BN/2). K-chunk 64.
// NSTAGE=2: classic double buffer (2 barriers/chunk).
// NSTAGE=3: triple buffer, ONE barrier per chunk, 2 chunks of cp.async ahead.
// OUTMODE: 0 = fp32, 1 = fp16 hi, 2 = fp16 hi+lo split.
template <int BN, bool SA, bool SB, bool HASALPHA, bool RELU, int OUTMODE, int NSTAGE>
__global__ __launch_bounds__(256, 2)
void hmma_gemm_kernel(const __half* __restrict__ Ah, const __half* __restrict__ Al,
                      long long sA, int lda,
                      const __half* __restrict__ Bh, const __half* __restrict__ Bl,
                      long long sB,
                      const float* __restrict__ alpha,
                      const float* __restrict__ bias, int sBias,
                      float* __restrict__ Cf, __half* __restrict__ Ch,
                      __half* __restrict__ Cl,
                      long long sC, int ldc, int K) {
    constexpr int TA = 16384;                 // 128 rows x 128 B
    constexpr int TB = BN * 128;
    constexpr int OFF_AL = TA;                // iff SA
    constexpr int OFF_B  = (SA ? 2 : 1) * TA;
    constexpr int OFF_BL = OFF_B + TB;        // iff SB
    constexpr int BUF = OFF_B + (SB ? 2 : 1) * TB;
    constexpr int NF = BN / 16;               // n8-frags per warp
    constexpr int NG = BN / 32;               // B ldmatrix groups per warp

    extern __shared__ char smem[];
    const uint32_t sb = smem_to_u32(smem);
    const int tid = threadIdx.x;
    const int lane = tid & 31;
    const int w = tid >> 5;
    const int wm = (w >> 1) * 32;
    const int wn = (w & 1) * (BN / 2);
    const int head = blockIdx.z;
    const int mBase = blockIdx.y * 128;
    const int nBase = blockIdx.x * BN;

    const __half* pA  = Ah + (long long)head * sA + (long long)mBase * lda;
    const __half* pAl = SA ? Al + (long long)head * sA + (long long)mBase * lda : nullptr;
    const __half* pB  = Bh + (long long)head * sB + (long long)nBase * K;
    const __half* pBl = SB ? Bl + (long long)head * sB + (long long)nBase * K : nullptr;

    float acc[2][NF][4];
#pragma unroll
    for (int mi = 0; mi < 2; mi++)
#pragma unroll
        for (int n = 0; n < NF; n++)
#pragma unroll
            for (int q = 0; q < 4; q++) acc[mi][n][q] = 0.0f;

    const int nCh = K >> 6;

    auto load_chunk = [&](uint32_t buf, int kB) {
#pragma unroll
        for (int u = tid; u < 1024; u += 256) {       // A rows: 128
            const int r = u >> 3, c = u & 7;
            const uint32_t sw = swz128((uint32_t)(r * 128 + c * 16));
            cp_async16(buf + sw, pA + (long long)r * lda + kB + c * 8);
            if (SA) cp_async16(buf + OFF_AL + sw, pAl + (long long)r * lda + kB + c * 8);
        }
#pragma unroll
        for (int u = tid; u < BN * 8; u += 256) {     // B rows: BN
            const int r = u >> 3, c = u & 7;
            const uint32_t sw = swz128((uint32_t)(r * 128 + c * 16));
            cp_async16(buf + OFF_B + sw, pB + (long long)r * K + kB + c * 8);
            if (SB) cp_async16(buf + OFF_BL + sw, pBl + (long long)r * K + kB + c * 8);
        }
    };

    // prologue: fill NSTAGE-1 buffers
#pragma unroll
    for (int s = 0; s < NSTAGE - 1; ++s) {
        if (s < nCh) { load_chunk(sb + s * BUF, s * 64); CP_COMMIT(); }
    }

    const int aRowA = wm + (lane & 15);
    const int aRowB = wn + (lane & 15);
    const int cSel  = (lane >> 4);

    for (int c = 0; c < nCh; ++c) {
        if (NSTAGE == 3) {
            if (c + 1 < nCh) { CP_WAIT(1); } else { CP_WAIT(0); }
            __syncthreads();   // chunk c ready AND buffer (c+2)%3 drained by all
            if (c + 2 < nCh) {
                load_chunk(sb + ((c + 2) % 3) * BUF, (c + 2) * 64);
                CP_COMMIT();
            }
        } else {
            if (c + 1 < nCh) {
                load_chunk(sb + ((c + 1) & 1) * BUF, (c + 1) * 64);
                CP_COMMIT();
                CP_WAIT(1);
            } else {
                CP_WAIT(0);
            }
            __syncthreads();
        }

        const uint32_t bA = sb + (c % NSTAGE) * BUF;

#pragma unroll
        for (int ks = 0; ks < 4; ks++) {
            const int kc = ks * 2 + cSel;
            uint32_t ah[2][4], al[2][4];
#pragma unroll
            for (int mi = 0; mi < 2; mi++) {
                const uint32_t ad = swz128((uint32_t)((aRowA + mi * 16) * 128 + kc * 16));
                LDMX4(ah[mi], bA + ad);
                if (SA) LDMX4(al[mi], bA + OFF_AL + ad);
            }
#pragma unroll
            for (int g = 0; g < NG; g++) {
                uint32_t bh[4], bl[4];
                const uint32_t bd = swz128((uint32_t)((aRowB + g * 16) * 128 + kc * 16));
                LDMX4(bh, bA + OFF_B + bd);
                if (SB) LDMX4(bl, bA + OFF_BL + bd);
#pragma unroll
                for (int mi = 0; mi < 2; mi++)
#pragma unroll
                    for (int s = 0; s < 2; s++) {
                        const int n = g * 2 + s;
                        MMA_F16(acc[mi][n], ah[mi], bh[s], bh[s + 2]);
                        if (SB) MMA_F16(acc[mi][n], ah[mi], bl[s], bl[s + 2]);
                        if (SA) MMA_F16(acc[mi][n], al[mi], bh[s], bh[s + 2]);
                    }
            }
        }
        if (NSTAGE == 2) __syncthreads();
    }

    // -------------------------------- epilogue ------------------------------
    const float* bp = bias + (long long)head * sBias + nBase;
    const float* ap = HASALPHA ? alpha + nBase : nullptr;
#pragma unroll
    for (int mi = 0; mi < 2; mi++) {
        const int r0 = mBase + wm + mi * 16 + (lane >> 2);
#pragma unroll
        for (int n = 0; n < NF; n++) {
            const int colL = wn + n * 8 + (lane & 3) * 2;
            const float b0 = __ldg(bp + colL);
            const float b1 = __ldg(bp + colL + 1);
            float a0c = 1.0f, a1c = 1.0f;
            if (HASALPHA) { a0c = __ldg(ap + colL); a1c = __ldg(ap + colL + 1); }
#pragma unroll
            for (int rr = 0; rr < 2; rr++) {
                float v0 = HASALPHA ? fmaf(acc[mi][n][rr * 2 + 0], a0c, b0)
                                    : acc[mi][n][rr * 2 + 0] + b0;
                float v1 = HASALPHA ? fmaf(acc[mi][n][rr * 2 + 1], a1c, b1)
                                    : acc[mi][n][rr * 2 + 1] + b1;
                if (RELU) { v0 = fmaxf(v0, 0.0f); v1 = fmaxf(v1, 0.0f); }
                const long long o = (long long)head * sC +
                                    (long long)(r0 + rr * 8) * ldc + nBase + colL;
                if (OUTMODE == 0) {
                    *(float2*)(Cf + o) = make_float2(v0, v1);
                } else if (OUTMODE == 1) {
                    *(uint32_t*)(Ch + o) = pack_h2(__float2half(v0), __float2half(v1));
                } else {
                    __half h0 = __float2half(v0), h1 = __float2half(v1);
                    *(uint32_t*)(Ch + o) = pack_h2(h0, h1);
                    *(uint32_t*)(Cl + o) =
                        pack_h2(__float2half(v0 - __half2float(h0)),
                                __float2half(v1 - __half2float(h1)));
                }
            }
        }
    }
}

// ================================ launcher ==================================
extern "C" void kernel_launch(void* const* d_in, const int* in_sizes, int n_in,
                              void* d_out, int out_size) {
    const float* x   = (const float*)d_in[0];
    const float* W0  = (const float*)d_in[1];
    const float* b0  = (const float*)d_in[2];
    const float* g0  = (const float*)d_in[3];
    const float* be0 = (const float*)d_in[4];
    const float* m0  = (const float*)d_in[5];
    const float* v0  = (const float*)d_in[6];
    const float* W1  = (const float*)d_in[7];
    const float* b1  = (const float*)d_in[8];
    const float* g1  = (const float*)d_in[9];
    const float* be1 = (const float*)d_in[10];
    const float* m1  = (const float*)d_in[11];
    const float* v1  = (const float*)d_in[12];
    const float* HW1 = (const float*)d_in[13];
    const float* Hb1 = (const float*)d_in[14];
    const float* HW2 = (const float*)d_in[15];
    const float* Hb2 = (const float*)d_in[16];
    float* out = (float*)d_out;

    float *a0, *bb0, *a1, *bb1;
    __half *xh, *xl, *w0th, *w0tl, *hh, *hl, *w1th, *w1tl, *fh, *hw1t, *hw2t, *zh;
    cudaGetSymbolAddress((void**)&xh,   g_xh);
    cudaGetSymbolAddress((void**)&xl,   g_xl);
    cudaGetSymbolAddress((void**)&w0th, g_w0th);
    cudaGetSymbolAddress((void**)&w0tl, g_w0tl);
    cudaGetSymbolAddress((void**)&hh,   g_hh);
    cudaGetSymbolAddress((void**)&hl,   g_hl);
    cudaGetSymbolAddress((void**)&w1th, g_w1th);
    cudaGetSymbolAddress((void**)&w1tl, g_w1tl);
    cudaGetSymbolAddress((void**)&fh,   g_fh);
    cudaGetSymbolAddress((void**)&hw1t, g_hw1t);
    cudaGetSymbolAddress((void**)&hw2t, g_hw2t);
    cudaGetSymbolAddress((void**)&zh,   g_zh);
    cudaGetSymbolAddress((void**)&a0,   g_a0);
    cudaGetSymbolAddress((void**)&bb0,  g_bb0);
    cudaGetSymbolAddress((void**)&a1,   g_a1);
    cudaGetSymbolAddress((void**)&bb1,  g_bb1);

    cudaFuncSetAttribute(hmma_gemm_kernel<64, true, true, true, true, 2, 2>,
                         cudaFuncAttributeMaxDynamicSharedMemorySize, 98304);
    cudaFuncSetAttribute(hmma_gemm_kernel<64, true, true, true, true, 1, 2>,
                         cudaFuncAttributeMaxDynamicSharedMemorySize, 98304);
    cudaFuncSetAttribute(hmma_gemm_kernel<128, false, false, false, true, 1, 3>,
                         cudaFuncAttributeMaxDynamicSharedMemorySize, 98304);
    cudaFuncSetAttribute(hmma_gemm_kernel<128, false, false, false, false, 0, 3>,
                         cudaFuncAttributeMaxDynamicSharedMemorySize, 98304);

    // 0) single fused prep launch
    prep_all_kernel<<<21640, 256>>>(x, W0, W1, HW1, HW2,
                                    b0, g0, be0, m0, v0, b1, g1, be1, m1, v1);

    // 1) h = relu(BN(x @ W0 + b0))   3-pass split HMMA -> fp16 hi/lo
    hmma_gemm_kernel<64, true, true, true, true, 2, 2><<<dim3(32, 8, 1), 256, 98304>>>(
        xh, xl, 0LL, 256,
        w0th, w0tl, 0LL,
        a0, bb0, 0,
        nullptr, hh, hl, 0LL, 2048, 256);

    // 2) feats = relu(BN(h @ W1 + b1))  3-pass split HMMA -> fp16
    hmma_gemm_kernel<64, true, true, true, true, 1, 2><<<dim3(16, 8, 1), 256, 98304>>>(
        hh, hl, 0LL, 2048,
        w1th, w1tl, 0LL,
        a1, bb1, 0,
        nullptr, fh, nullptr, 0LL, 1024, 2048);

    // 3) z[n] = relu(feats @ HW1[n] + Hb1[n])  1-pass fp16, 3-stage pipe
    hmma_gemm_kernel<128, false, false, false, true, 1, 3><<<dim3(4, 8, 128), 256, 98304>>>(
        fh, nullptr, 0LL, 1024,
        hw1t, nullptr, 512LL * 1024,
        nullptr, Hb1, 512,
        nullptr, zh, nullptr, 1024LL * 512, 512, 1024);

    // 4) out[:,n,:] = z[n] @ HW2[n] + Hb2[n]  1-pass fp16 -> fp32, 3-stage pipe
    hmma_gemm_kernel<128, false, false, false, false, 0, 3><<<dim3(2, 8, 128), 256, 98304>>>(
        zh, nullptr, 1024LL * 512, 512,
        hw2t, nullptr, 256LL * 512,
        nullptr, Hb2, 256,
        out, nullptr, nullptr, 256LL, 128 * 256, 512);
}